// round 2
// baseline (speedup 1.0000x reference)
#include <cuda_runtime.h>
#include <cstdint>

#define NV    64
#define TMAX  2048
#define EDIM  512
#define HDIM  64
#define G3    192   // 3*H

// ---------------- scratch (static __device__, no allocations) ----------------
__device__ float g_xg[(size_t)NV * TMAX * G3];   // [V][T][192] precomputed input gates (+b_ih)
__device__ float g_hT[NV * HDIM];                // final hidden states, concat order v*H+j

// ---------------- packed f32x2 helpers ----------------
__device__ __forceinline__ void ffma2(unsigned long long &d, unsigned long long a, unsigned long long b) {
    asm volatile("fma.rn.f32x2 %0, %1, %2, %0;" : "+l"(d) : "l"(a), "l"(b));
}
__device__ __forceinline__ unsigned long long pack2(float x, float y) {
    unsigned long long r;
    asm("mov.b64 %0, {%1, %2};" : "=l"(r) : "r"(__float_as_uint(x)), "r"(__float_as_uint(y)));
    return r;
}
__device__ __forceinline__ float hsum2(unsigned long long d) {
    unsigned int a, b;
    asm("mov.b64 {%0, %1}, %2;" : "=r"(a), "=r"(b) : "l"(d));
    return __uint_as_float(a) + __uint_as_float(b);
}
__device__ __forceinline__ void unpack2(unsigned long long d, float &x, float &y) {
    unsigned int a, b;
    asm("mov.b64 {%0, %1}, %2;" : "=r"(a), "=r"(b) : "l"(d));
    x = __uint_as_float(a); y = __uint_as_float(b);
}
__device__ __forceinline__ void cp_async4(void* dst_smem, const void* src) {
    unsigned int d = (unsigned int)__cvta_generic_to_shared(dst_smem);
    asm volatile("cp.async.ca.shared.global [%0], [%1], 4;" :: "r"(d), "l"(src));
}

// =====================================================================
// Kernel 1: x_gates GEMM.  C[m,n] = sum_e A[m,e]*W_ih[n,e] + b_ih[n]
// A = emb flattened [V*T, E]; tiles fully past lengths[v] are skipped.
// Block tile: 64(M) x 192(N) x 32(K), 256 threads, 4x12 microtile via f32x2.
// =====================================================================
__global__ __launch_bounds__(256) void gemm_kernel(
    const float* __restrict__ emb, const int* __restrict__ lengths,
    const float* __restrict__ W_ih, const float* __restrict__ b_ih)
{
    const int v  = blockIdx.y;
    const int tt = blockIdx.x;
    if (tt * 64 >= lengths[v]) return;   // h frozen past len: these x_gates never read

    __shared__ __align__(16) float As[32][64];
    __shared__ __align__(16) float Bs[32][192];

    const int tid = threadIdx.x;
    const int tm = tid >> 4;        // 0..15 -> rows tm*4..tm*4+3
    const int tn = tid & 15;        // 0..15 -> cols tn*12..tn*12+11

    const float* Abase = emb + ((size_t)v * TMAX + (size_t)tt * 64) * EDIM;

    unsigned long long acc[4][6];
#pragma unroll
    for (int i = 0; i < 4; i++)
#pragma unroll
        for (int j = 0; j < 6; j++) acc[i][j] = 0ull;

    const int ar = tid >> 2;   // 0..63 A row
    const int aq = tid & 3;    // 0..3  A quad

    for (int k0 = 0; k0 < EDIM; k0 += 32) {
        // global loads into registers
        float4 a0 = *(const float4*)(Abase + (size_t)ar * EDIM + k0 + aq * 4);
        float4 a1 = *(const float4*)(Abase + (size_t)ar * EDIM + k0 + aq * 4 + 16);
        float4 bb[8];
        if (tid < 192) {
            const float* Bp = W_ih + (size_t)tid * EDIM + k0;
#pragma unroll
            for (int j = 0; j < 8; j++) bb[j] = *(const float4*)(Bp + j * 4);
        }
        __syncthreads();   // previous tile's compute done
        // stores to shared (A transposed to [k][m], B transposed to [k][n])
        As[aq * 4 + 0][ar] = a0.x;  As[aq * 4 + 1][ar] = a0.y;
        As[aq * 4 + 2][ar] = a0.z;  As[aq * 4 + 3][ar] = a0.w;
        As[aq * 4 + 16][ar] = a1.x; As[aq * 4 + 17][ar] = a1.y;
        As[aq * 4 + 18][ar] = a1.z; As[aq * 4 + 19][ar] = a1.w;
        if (tid < 192) {
#pragma unroll
            for (int j = 0; j < 8; j++) {
                Bs[j * 4 + 0][tid] = bb[j].x;
                Bs[j * 4 + 1][tid] = bb[j].y;
                Bs[j * 4 + 2][tid] = bb[j].z;
                Bs[j * 4 + 3][tid] = bb[j].w;
            }
        }
        __syncthreads();
        // compute
#pragma unroll 8
        for (int kk = 0; kk < 32; kk++) {
            float4 av = *(const float4*)&As[kk][tm * 4];
            unsigned long long ad0 = pack2(av.x, av.x);
            unsigned long long ad1 = pack2(av.y, av.y);
            unsigned long long ad2 = pack2(av.z, av.z);
            unsigned long long ad3 = pack2(av.w, av.w);
            const unsigned long long* bp = (const unsigned long long*)&Bs[kk][tn * 12];
#pragma unroll
            for (int j = 0; j < 6; j++) {
                unsigned long long bv = bp[j];
                ffma2(acc[0][j], ad0, bv);
                ffma2(acc[1][j], ad1, bv);
                ffma2(acc[2][j], ad2, bv);
                ffma2(acc[3][j], ad3, bv);
            }
        }
    }

    // epilogue: +bias, store to g_xg
    float bias[12];
    *(float4*)&bias[0] = *(const float4*)(b_ih + tn * 12 + 0);
    *(float4*)&bias[4] = *(const float4*)(b_ih + tn * 12 + 4);
    *(float4*)&bias[8] = *(const float4*)(b_ih + tn * 12 + 8);
#pragma unroll
    for (int i = 0; i < 4; i++) {
        size_t row = (size_t)v * TMAX + (size_t)tt * 64 + tm * 4 + i;
        float* outp = g_xg + row * G3 + tn * 12;
        float o[12];
#pragma unroll
        for (int j = 0; j < 6; j++) {
            float x, y; unpack2(acc[i][j], x, y);
            o[2 * j]     = x + bias[2 * j];
            o[2 * j + 1] = y + bias[2 * j + 1];
        }
        *(float4*)(outp + 0) = make_float4(o[0], o[1], o[2], o[3]);
        *(float4*)(outp + 4) = make_float4(o[4], o[5], o[6], o[7]);
        *(float4*)(outp + 8) = make_float4(o[8], o[9], o[10], o[11]);
    }
}

// =====================================================================
// Kernel 2: GRU scan. One CTA per variable, 384 threads = (gate 0..191) x (k-half 0..1).
// W_hh rows live in registers as f32x2 pairs; h broadcast via SMEM.
// x_gates streamed with a 4-deep cp.async ring.
// =====================================================================
__global__ __launch_bounds__(384) void scan_kernel(
    const int* __restrict__ lengths, const float* __restrict__ W_hh,
    const float* __restrict__ b_hh)
{
    const int v   = blockIdx.x;
    const int len = lengths[v];
    const int tid = threadIdx.x;
    const int gate = tid % G3;
    const int half = tid / G3;   // 0 or 1: k in [half*32, half*32+32)

    __shared__ __align__(16) float sh_h[HDIM];
    __shared__ __align__(16) float sh_part[384];
    __shared__ __align__(16) float sh_xg[4][G3];

    // W_hh row slice into registers (16 packed pairs = 32 fp32)
    unsigned long long w[16];
    {
        const unsigned long long* wp =
            (const unsigned long long*)(W_hh + (size_t)gate * HDIM + half * 32);
#pragma unroll
        for (int i = 0; i < 16; i++) w[i] = wp[i];
    }
    float br = 0.f, bz = 0.f, bn = 0.f;
    if (tid < HDIM) {
        br = b_hh[tid];
        bz = b_hh[tid + 64];
        bn = b_hh[tid + 128];
        sh_h[tid] = 0.f;
    }

    const float* xgbase = g_xg + (size_t)v * TMAX * G3;

    // prefill 4-deep cp.async ring with xg[0..3]
    if (tid < G3) {
#pragma unroll
        for (int i = 0; i < 4; i++) {
            cp_async4(&sh_xg[i][tid], xgbase + (size_t)i * G3 + tid);
            asm volatile("cp.async.commit_group;" ::: "memory");
        }
    }
    __syncthreads();

    for (int t = 0; t < len; t++) {
        asm volatile("cp.async.wait_group 3;" ::: "memory");

        // hg partial: 32-wide dot with h broadcast from SMEM
        unsigned long long a0 = 0ull, a1 = 0ull;
        const unsigned long long* hp = (const unsigned long long*)(sh_h + half * 32);
#pragma unroll
        for (int i = 0; i < 16; i += 2) {
            ffma2(a0, w[i],     hp[i]);
            ffma2(a1, w[i + 1], hp[i + 1]);
        }
        sh_part[tid] = hsum2(a0) + hsum2(a1);
        __syncthreads();

        if (tid < HDIM) {
            const int buf = t & 3;
            float hr = sh_part[tid]       + sh_part[tid + 192] + br;
            float hz = sh_part[tid + 64]  + sh_part[tid + 256] + bz;
            float hn = sh_part[tid + 128] + sh_part[tid + 320] + bn;
            float xr = sh_xg[buf][tid];
            float xz = sh_xg[buf][tid + 64];
            float xn = sh_xg[buf][tid + 128];
            float r = 1.f / (1.f + __expf(-(xr + hr)));
            float z = 1.f / (1.f + __expf(-(xz + hz)));
            float pre = xn + r * hn;
            float n = 1.f - 2.f / (1.f + __expf(2.f * pre));   // tanh(pre)
            float h = sh_h[tid];
            sh_h[tid] = n + z * (h - n);                       // (1-z)*n + z*h
        }
        __syncthreads();

        // refill the buffer we just consumed with xg[t+4]
        if (tid < G3) {
            int idx = t + 4; if (idx > TMAX - 1) idx = TMAX - 1;
            cp_async4(&sh_xg[t & 3][tid], xgbase + (size_t)idx * G3 + tid);
            asm volatile("cp.async.commit_group;" ::: "memory");
        }
    }
    asm volatile("cp.async.wait_group 0;" ::: "memory");

    if (tid < HDIM) g_hT[v * HDIM + tid] = sh_h[tid];
}

// =====================================================================
// Kernel 3: MLP head. hid = relu(hT_flat @ W1^T + b1); out = hid @ W2^T + b2.
// =====================================================================
__global__ __launch_bounds__(256) void mlp_kernel(
    const float* __restrict__ W1, const float* __restrict__ b1,
    const float* __restrict__ W2, const float* __restrict__ b2,
    float* __restrict__ out)
{
    __shared__ float sh_hid[64];
    const int warp = threadIdx.x >> 5;
    const int lane = threadIdx.x & 31;

#pragma unroll
    for (int rep = 0; rep < 8; rep++) {
        const int i = warp * 8 + rep;
        const float* wrow = W1 + (size_t)i * (NV * HDIM);
        float s = 0.f;
        for (int k = lane * 4; k < NV * HDIM; k += 128) {
            float4 wv = *(const float4*)(wrow + k);
            float4 hv = *(const float4*)(g_hT + k);
            s += wv.x * hv.x + wv.y * hv.y + wv.z * hv.z + wv.w * hv.w;
        }
#pragma unroll
        for (int off = 16; off; off >>= 1) s += __shfl_xor_sync(0xffffffffu, s, off);
        if (lane == 0) sh_hid[i] = fmaxf(s + b1[i], 0.f);
    }
    __syncthreads();

    if (threadIdx.x < 32) {
        float s = sh_hid[lane] * W2[lane] + sh_hid[lane + 32] * W2[lane + 32];
#pragma unroll
        for (int off = 16; off; off >>= 1) s += __shfl_xor_sync(0xffffffffu, s, off);
        if (lane == 0) out[0] = s + b2[0];
    }
}

// =====================================================================
extern "C" void kernel_launch(void* const* d_in, const int* in_sizes, int n_in,
                              void* d_out, int out_size)
{
    const float* emb     = (const float*)d_in[0];
    const int*   lengths = (const int*)  d_in[1];
    const float* W_ih    = (const float*)d_in[2];
    const float* W_hh    = (const float*)d_in[3];
    const float* b_ih    = (const float*)d_in[4];
    const float* b_hh    = (const float*)d_in[5];
    const float* W1      = (const float*)d_in[6];
    const float* b1      = (const float*)d_in[7];
    const float* W2      = (const float*)d_in[8];
    const float* b2      = (const float*)d_in[9];

    dim3 ggrid(TMAX / 64, NV);
    gemm_kernel<<<ggrid, 256>>>(emb, lengths, W_ih, b_ih);
    scan_kernel<<<NV, 384>>>(lengths, W_hh, b_hh);
    mlp_kernel<<<1, 256>>>(W1, b1, W2, b2, (float*)d_out);
}

// round 4
// speedup vs baseline: 1.4573x; 1.4573x over previous
#include <cuda_runtime.h>
#include <cstdint>

#define NV    64
#define TMAX  2048
#define EDIM  512
#define HDIM  64
#define G3    192   // 3*H

// ---------------- scratch ----------------
__device__ float g_xg[(size_t)NV * TMAX * G3];   // [V][T][192] x_gates (+b_ih)
__device__ float g_hT[NV * HDIM];
__device__ float g_Wt[EDIM * G3];                // W_ih transposed: [e][n]

// ---------------- helpers ----------------
typedef unsigned long long ull;
__device__ __forceinline__ void ffma2(ull &d, ull a, ull b) {
    asm volatile("fma.rn.f32x2 %0, %1, %2, %0;" : "+l"(d) : "l"(a), "l"(b));
}
__device__ __forceinline__ float hsum2(ull d) {
    unsigned int a, b;
    asm("mov.b64 {%0, %1}, %2;" : "=r"(a), "=r"(b) : "l"(d));
    return __uint_as_float(a) + __uint_as_float(b);
}
__device__ __forceinline__ void unpack2(ull d, float &x, float &y) {
    unsigned int a, b;
    asm("mov.b64 {%0, %1}, %2;" : "=r"(a), "=r"(b) : "l"(d));
    x = __uint_as_float(a); y = __uint_as_float(b);
}
__device__ __forceinline__ void cp_async4(void* dst, const void* src) {
    unsigned int d = (unsigned int)__cvta_generic_to_shared(dst);
    asm volatile("cp.async.ca.shared.global [%0], [%1], 4;" :: "r"(d), "l"(src));
}
__device__ __forceinline__ void cp_async16(void* dst, const void* src) {
    unsigned int d = (unsigned int)__cvta_generic_to_shared(dst);
    asm volatile("cp.async.ca.shared.global [%0], [%1], 16;" :: "r"(d), "l"(src));
}

// =====================================================================
// Kernel 0: transpose W_ih [192,512] -> g_Wt [512,192]
// =====================================================================
__global__ __launch_bounds__(256) void transpose_wih(const float* __restrict__ W_ih)
{
    int idx = blockIdx.x * 256 + threadIdx.x;
    if (idx < EDIM * G3) {
        int e = idx / G3, n = idx - e * G3;
        g_Wt[idx] = W_ih[(size_t)n * EDIM + e];
    }
}

// =====================================================================
// Kernel 1: x_gates GEMM. Block 64(M) x 192(N) x 32(K), 128 threads,
// 8x12 microtile via f32x2 (A duplicated-pair SMEM, B cp.async from g_Wt).
// Tiles fully past lengths[v] are skipped (never consumed by the scan).
// =====================================================================
__global__ __launch_bounds__(128, 3) void gemm_kernel(
    const float* __restrict__ emb, const int* __restrict__ lengths,
    const float* __restrict__ b_ih)
{
    const int v  = blockIdx.y;
    const int tt = blockIdx.x;
    if (tt * 64 >= lengths[v]) return;

    __shared__ __align__(16) float2 Asd[32][64];   // [k][m] duplicated (a,a)
    __shared__ __align__(16) float  Bs[32][192];   // [k][n]

    const int tid = threadIdx.x;
    const int tm = tid >> 4;        // 0..7  -> rows tm*8 .. +7
    const int tn = tid & 15;        // 0..15 -> cols tn*12 .. +11
    const int ar = tid >> 1;        // 0..63 A row for loading
    const int aq = tid & 1;         // k-half (16 floats)
    const int kb = tid >> 2;        // 0..31 B row (k)
    const int seg = tid & 3;        // 48-float segment

    const float* Ag = emb + ((size_t)v * TMAX + (size_t)tt * 64 + ar) * EDIM + aq * 16;
    const float* Bg = g_Wt + (size_t)kb * G3 + seg * 48;

    float4 aR[4];
#pragma unroll
    for (int i = 0; i < 4; i++) aR[i] = *(const float4*)(Ag + i * 4);

    ull acc[8][6];
#pragma unroll
    for (int i = 0; i < 8; i++)
#pragma unroll
        for (int j = 0; j < 6; j++) acc[i][j] = 0ull;

    for (int k0 = 0; k0 < EDIM; k0 += 32) {
        __syncthreads();   // previous tile's compute done
        // B: direct async copy (already [k][n] in g_Wt)
        const float* bsrc = Bg + (size_t)k0 * G3;
#pragma unroll
        for (int i = 0; i < 12; i++)
            cp_async16(&Bs[kb][seg * 48 + i * 4], bsrc + i * 4);
        asm volatile("cp.async.commit_group;" ::: "memory");
        // A: duplicated-pair stores
#pragma unroll
        for (int i = 0; i < 4; i++) {
            Asd[aq * 16 + i * 4 + 0][ar] = make_float2(aR[i].x, aR[i].x);
            Asd[aq * 16 + i * 4 + 1][ar] = make_float2(aR[i].y, aR[i].y);
            Asd[aq * 16 + i * 4 + 2][ar] = make_float2(aR[i].z, aR[i].z);
            Asd[aq * 16 + i * 4 + 3][ar] = make_float2(aR[i].w, aR[i].w);
        }
        // prefetch next A tile (overlaps compute)
        if (k0 + 32 < EDIM) {
#pragma unroll
            for (int i = 0; i < 4; i++) aR[i] = *(const float4*)(Ag + k0 + 32 + i * 4);
        }
        asm volatile("cp.async.wait_group 0;" ::: "memory");
        __syncthreads();   // all threads' copies + stores visible
        // compute
#pragma unroll 4
        for (int kk = 0; kk < 32; kk++) {
            ull a8[8];
            const ull* ap = (const ull*)&Asd[kk][tm * 8];
#pragma unroll
            for (int i = 0; i < 8; i++) a8[i] = ap[i];
            ull b6[6];
            const ull* bp = (const ull*)&Bs[kk][tn * 12];
#pragma unroll
            for (int j = 0; j < 6; j++) b6[j] = bp[j];
#pragma unroll
            for (int i = 0; i < 8; i++)
#pragma unroll
                for (int j = 0; j < 6; j++) ffma2(acc[i][j], a8[i], b6[j]);
        }
    }

    // epilogue: +bias, store
    float bias[12];
    *(float4*)&bias[0] = *(const float4*)(b_ih + tn * 12 + 0);
    *(float4*)&bias[4] = *(const float4*)(b_ih + tn * 12 + 4);
    *(float4*)&bias[8] = *(const float4*)(b_ih + tn * 12 + 8);
#pragma unroll
    for (int i = 0; i < 8; i++) {
        size_t row = (size_t)v * TMAX + (size_t)tt * 64 + tm * 8 + i;
        float* outp = g_xg + row * G3 + tn * 12;
        float o[12];
#pragma unroll
        for (int j = 0; j < 6; j++) {
            float x, y; unpack2(acc[i][j], x, y);
            o[2 * j]     = x + bias[2 * j];
            o[2 * j + 1] = y + bias[2 * j + 1];
        }
        *(float4*)(outp + 0) = make_float4(o[0], o[1], o[2], o[3]);
        *(float4*)(outp + 4) = make_float4(o[4], o[5], o[6], o[7]);
        *(float4*)(outp + 8) = make_float4(o[8], o[9], o[10], o[11]);
    }
}

// =====================================================================
// Kernel 2: GRU scan. 128 threads = (j 0..63) x (half 0..1), lanes 2j/2j+1
// adjacent for shfl pair-reduce. Each thread computes all 3 gate rows of j
// over its 32-wide k-half (48 FFMA2 = fma-pipe floor).
// ONE barrier per step, placed AFTER the per-thread cp.async wait so that
// every thread's async copies are globally visible before anyone reads them
// (fixes the round-3 visibility race).
// =====================================================================
__global__ __launch_bounds__(128) void scan_kernel(
    const int* __restrict__ lengths, const float* __restrict__ W_hh,
    const float* __restrict__ b_hh)
{
    const int v   = blockIdx.x;
    const int len = lengths[v];
    const int tid = threadIdx.x;
    const int j    = tid >> 1;
    const int half = tid & 1;

    __shared__ __align__(16) float sh_h[2][HDIM];
    __shared__ __align__(16) float sh_xg[4][G3];

    // W_hh rows j, 64+j, 128+j (k-half slice) as f32x2 pairs
    ull wr[16], wz[16], wn[16];
    {
        const ull* pr = (const ull*)(W_hh + (size_t)(j)       * HDIM + half * 32);
        const ull* pz = (const ull*)(W_hh + (size_t)(64 + j)  * HDIM + half * 32);
        const ull* pn = (const ull*)(W_hh + (size_t)(128 + j) * HDIM + half * 32);
#pragma unroll
        for (int i = 0; i < 16; i++) { wr[i] = pr[i]; wz[i] = pz[i]; wn[i] = pn[i]; }
    }
    const float br = b_hh[j], bz = b_hh[64 + j], bn = b_hh[128 + j];
    float myh = 0.f;
    if (tid < HDIM) sh_h[0][tid] = 0.f;

    const float* xgbase = g_xg + (size_t)v * TMAX * G3;

    // prefill 3 buffers (data 0,1,2), one commit group each
#pragma unroll
    for (int i = 0; i < 3; i++) {
        cp_async4(&sh_xg[i][tid], xgbase + (size_t)i * G3 + tid);
        if (tid < 64) cp_async4(&sh_xg[i][128 + tid], xgbase + (size_t)i * G3 + 128 + tid);
        asm volatile("cp.async.commit_group;" ::: "memory");
    }
    // data 0 ready for THIS thread, then barrier -> ready for ALL threads
    asm volatile("cp.async.wait_group 2;" ::: "memory");
    __syncthreads();

    for (int t = 0; t < len; t++) {
        const int buf = t & 3;
        float xr = sh_xg[buf][j];
        float xz = sh_xg[buf][64 + j];
        float xn = sh_xg[buf][128 + j];

        // matvec partials over this thread's k-half
        const ull* hp = (const ull*)(&sh_h[t & 1][half * 32]);
        ull h8[16];
#pragma unroll
        for (int i = 0; i < 16; i++) h8[i] = hp[i];
        ull ar0 = 0ull, ar1 = 0ull, az0 = 0ull, az1 = 0ull, an0 = 0ull, an1 = 0ull;
#pragma unroll
        for (int i = 0; i < 16; i += 2) {
            ffma2(ar0, wr[i],     h8[i]);
            ffma2(az0, wz[i],     h8[i]);
            ffma2(an0, wn[i],     h8[i]);
            ffma2(ar1, wr[i + 1], h8[i + 1]);
            ffma2(az1, wz[i + 1], h8[i + 1]);
            ffma2(an1, wn[i + 1], h8[i + 1]);
        }
        float sr = hsum2(ar0) + hsum2(ar1);
        float sz = hsum2(az0) + hsum2(az1);
        float sn = hsum2(an0) + hsum2(an1);
        // combine k-halves across lane pair
        sr += __shfl_xor_sync(0xffffffffu, sr, 1);
        sz += __shfl_xor_sync(0xffffffffu, sz, 1);
        sn += __shfl_xor_sync(0xffffffffu, sn, 1);

        // gate math (both lanes compute identical result)
        float rr = __fdividef(1.f, 1.f + __expf(-(xr + sr + br)));
        float zz = __fdividef(1.f, 1.f + __expf(-(xz + sz + bz)));
        float pre = xn + rr * (sn + bn);
        float nn = 1.f - __fdividef(2.f, 1.f + __expf(2.f * pre));   // tanh(pre)
        myh = nn + zz * (myh - nn);
        if (half == 0) sh_h[(t + 1) & 1][j] = myh;

        // refill: data t+3 into buffer (t+3)&3 (its step-(t-1) reads are
        // separated from this write by the step-(t-1) end barrier)
        {
            int src = t + 3; if (src > TMAX - 1) src = TMAX - 1;
            const float* sp = xgbase + (size_t)src * G3;
            cp_async4(&sh_xg[(t + 3) & 3][tid], sp + tid);
            if (tid < 64) cp_async4(&sh_xg[(t + 3) & 3][128 + tid], sp + 128 + tid);
            asm volatile("cp.async.commit_group;" ::: "memory");
        }
        // my copies of data t+1 complete, then barrier: everyone's complete,
        // and the sh_h write above is visible. ONE barrier per step.
        asm volatile("cp.async.wait_group 2;" ::: "memory");
        __syncthreads();
    }
    asm volatile("cp.async.wait_group 0;" ::: "memory");

    if (half == 0) g_hT[v * HDIM + j] = myh;
}

// =====================================================================
// Kernel 3: MLP head.
// =====================================================================
__global__ __launch_bounds__(256) void mlp_kernel(
    const float* __restrict__ W1, const float* __restrict__ b1,
    const float* __restrict__ W2, const float* __restrict__ b2,
    float* __restrict__ out)
{
    __shared__ float sh_hid[64];
    const int warp = threadIdx.x >> 5;
    const int lane = threadIdx.x & 31;

#pragma unroll
    for (int rep = 0; rep < 8; rep++) {
        const int i = warp * 8 + rep;
        const float* wrow = W1 + (size_t)i * (NV * HDIM);
        float s = 0.f;
        for (int k = lane * 4; k < NV * HDIM; k += 128) {
            float4 wv = *(const float4*)(wrow + k);
            float4 hv = *(const float4*)(g_hT + k);
            s += wv.x * hv.x + wv.y * hv.y + wv.z * hv.z + wv.w * hv.w;
        }
#pragma unroll
        for (int off = 16; off; off >>= 1) s += __shfl_xor_sync(0xffffffffu, s, off);
        if (lane == 0) sh_hid[i] = fmaxf(s + b1[i], 0.f);
    }
    __syncthreads();

    if (threadIdx.x < 32) {
        float s = sh_hid[lane] * W2[lane] + sh_hid[lane + 32] * W2[lane + 32];
#pragma unroll
        for (int off = 16; off; off >>= 1) s += __shfl_xor_sync(0xffffffffu, s, off);
        if (lane == 0) out[0] = s + b2[0];
    }
}

// =====================================================================
extern "C" void kernel_launch(void* const* d_in, const int* in_sizes, int n_in,
                              void* d_out, int out_size)
{
    const float* emb     = (const float*)d_in[0];
    const int*   lengths = (const int*)  d_in[1];
    const float* W_ih    = (const float*)d_in[2];
    const float* W_hh    = (const float*)d_in[3];
    const float* b_ih    = (const float*)d_in[4];
    const float* b_hh    = (const float*)d_in[5];
    const float* W1      = (const float*)d_in[6];
    const float* b1      = (const float*)d_in[7];
    const float* W2      = (const float*)d_in[8];
    const float* b2      = (const float*)d_in[9];

    transpose_wih<<<(EDIM * G3 + 255) / 256, 256>>>(W_ih);
    dim3 ggrid(TMAX / 64, NV);
    gemm_kernel<<<ggrid, 128>>>(emb, lengths, b_ih);
    scan_kernel<<<NV, 128>>>(lengths, W_hh, b_hh);
    mlp_kernel<<<1, 256>>>(W1, b1, W2, b2, (float*)d_out);
}